// round 12
// baseline (speedup 1.0000x reference)
#include <cuda_runtime.h>
#include <math.h>

#define IC 128
#define NC 5
#define DD 153
#define DP 160      // padded capsule dim
#define DDP 160     // padded d-dim for hmT
#define CD 765
#define CDP 768     // padded row stride for GEMM outputs / Wp
#define ROWP 800    // NC*DP
#define KD 768
#define NQV 256
#define EPSF 1e-8f
#define NCHUNK 5
#define DCH 32      // DDP / NCHUNK
#define GQ 2        // queries per routing block

__device__ __align__(16) float g_hm[IC * CDP];        // hat_m fp32 (GEMM out)
__device__ __align__(16) float g_hq[NQV * CDP];       // hat_q fp32
__device__ __align__(16) float g_hmT[NC * DDP * IC];  // [c][dpad][i] fp32
__device__ __align__(16) float g_hmP[IC * ROWP];      // [i][c][dp] fp32, pads 0
__device__ __align__(16) float g_mean[NC * IC];       // [c][i]
__device__ __align__(16) float g_norm[NC * IC];       // [c][i]
__device__ __align__(16) float g_Wp[KD * CDP];        // zero-padded W

__device__ __forceinline__ float warp_sum(float v) {
#pragma unroll
  for (int o = 16; o; o >>= 1) v += __shfl_xor_sync(0xffffffffu, v, o);
  return v;
}

// ---------------------------------------------------------------------------
// Pad W [768][765] -> Wp [768][768]
// ---------------------------------------------------------------------------
__global__ __launch_bounds__(256) void wpad_kernel(const float* __restrict__ W,
                                                   float* __restrict__ Wp) {
  int idx = blockIdx.x * 256 + threadIdx.x;
  if (idx < KD * CDP) {
    int k = idx / CDP, c = idx - k * CDP;
    Wp[idx] = (c < CD) ? W[k * CD + c] : 0.f;
  }
}

// ---------------------------------------------------------------------------
// GEMM: 32x32 tiles, grid (24,12)=288 blocks, 128 threads, 4x2 reg tile.
// ---------------------------------------------------------------------------
#define BM 32
#define BN 32
#define BK 32

__global__ __launch_bounds__(128) void gemm_kernel(
    const float* __restrict__ Am, const float* __restrict__ Aq,
    const float* __restrict__ Wp, const float* __restrict__ bias,
    float* __restrict__ Om, float* __restrict__ Oq) {
  __shared__ float As[BK][BM];
  __shared__ float Bs[BK][BN];
  const int t = threadIdx.x;
  const int row0 = blockIdx.y * BM;
  const int c0 = blockIdx.x * BN;

  const float* A;
  float* O;
  if (row0 < IC) { A = Am + row0 * KD; O = Om + row0 * CDP; }
  else           { A = Aq + (row0 - IC) * KD; O = Oq + (row0 - IC) * CDP; }

  const int ar = t >> 3, akc = (t & 7) << 2;
  const int br = t >> 3, bc = (t & 7) << 2;
  const int ty = t >> 4, tx = t & 15;

  float acc[4][2] = {};

  for (int k0 = 0; k0 < KD; k0 += BK) {
#pragma unroll
    for (int h = 0; h < 2; ++h) {
      float4 av = *(const float4*)(A + (ar + 16 * h) * KD + k0 + akc);
      As[akc + 0][ar + 16 * h] = av.x;
      As[akc + 1][ar + 16 * h] = av.y;
      As[akc + 2][ar + 16 * h] = av.z;
      As[akc + 3][ar + 16 * h] = av.w;
      *(float4*)&Bs[br + 16 * h][bc] =
          *(const float4*)(Wp + (k0 + br + 16 * h) * CDP + c0 + bc);
    }
    __syncthreads();
#pragma unroll
    for (int kk = 0; kk < BK; ++kk) {
      float4 a4 = *(const float4*)&As[kk][ty << 2];
      float b0 = Bs[kk][tx << 1];
      float b1 = Bs[kk][(tx << 1) + 1];
      acc[0][0] += a4.x * b0; acc[0][1] += a4.x * b1;
      acc[1][0] += a4.y * b0; acc[1][1] += a4.y * b1;
      acc[2][0] += a4.z * b0; acc[2][1] += a4.z * b1;
      acc[3][0] += a4.w * b0; acc[3][1] += a4.w * b1;
    }
    __syncthreads();
  }

#pragma unroll
  for (int rr = 0; rr < 4; ++rr) {
    int lr = (ty << 2) + rr;
#pragma unroll
    for (int j = 0; j < 2; ++j) {
      int c = c0 + (tx << 1) + j;
      if (c < CD) O[lr * CDP + c] = acc[rr][j] + bias[c];
    }
  }
}

// ---------------------------------------------------------------------------
// Prep: blocks 0..79 = stats + hmP fp32; blocks 80..179 = transpose fp32
// into d-padded hmT (zero rows for d in [153,160)).
// ---------------------------------------------------------------------------
__global__ __launch_bounds__(256) void prep_kernel(
    const float* __restrict__ hm, float* __restrict__ hmP,
    float* __restrict__ hmT, float* __restrict__ meanA,
    float* __restrict__ normA) {
  const int t = threadIdx.x;
  if (blockIdx.x < 80) {
    int g = blockIdx.x * 8 + (t >> 5);
    int lane = t & 31;
    int i = g / NC, c = g - i * NC;
    const float* row = hm + i * CDP + c * DD;
    float vals[5];
    float s = 0.f, s2 = 0.f;
#pragma unroll
    for (int k = 0; k < 5; ++k) {
      int d = lane + 32 * k;
      float x = (d < DD) ? row[d] : 0.f;
      vals[k] = x;
      s += x;
      s2 += x * x;
    }
    s = warp_sum(s);
    s2 = warp_sum(s2);
    float mean = s * (1.f / DD);
    if (lane == 0) {
      meanA[c * IC + i] = mean;
      normA[c * IC + i] = sqrtf(fmaxf(s2 - DD * mean * mean, 0.f));
    }
#pragma unroll
    for (int k = 0; k < 5; ++k) {
      int d = lane + 32 * k;
      hmP[i * ROWP + c * DP + d] = vals[k];
    }
  } else {
    __shared__ float sm[32][33];
    int bx = blockIdx.x - 80;
    int c = bx / 20;
    int rem = bx - c * 20;
    int i0 = (rem / 5) * 32;
    int d0 = (rem % 5) * 32;
    int tx = t & 31, ty = t >> 5;
#pragma unroll
    for (int k = 0; k < 4; ++k) {
      int i = i0 + ty + 8 * k;
      int d = d0 + tx;
      sm[tx][ty + 8 * k] = (d < DD) ? hm[i * CDP + c * DD + d] : 0.f;
    }
    __syncthreads();
#pragma unroll
    for (int k = 0; k < 4; ++k) {
      int d = d0 + ty + 8 * k;
      hmT[(c * DDP + d) * IC + i0 + tx] = sm[ty + 8 * k][tx];  // zeros d>=153
    }
  }
}

// ---------------------------------------------------------------------------
// Routing v11: block per 2 queries, 1024 threads.
// num-recurrence: num_r = (num_{r-1} + mdv_r)/2 (tq_r=(tq_{r-1}+v_{r-1})/2,
// both dots against the same hm rows) -> phase A does ONE sweep per round:
//   r=0: num partials (dot hm . tq);  r>=1: mdv partials (dot hm . v).
// Partials share one buffer part6. Raw num kept per (qq,i,c) in num_s.
//   A: 25 warps (ch, c), BOTH queries, 4-d load batches.
//   I: t<256: r=0 init num_s/p/dsp; r>=1 mdv-sum, num recurrence, a/p/softmax.
//   B: t<800: thread per (qq,c,d2), 8-i batches over hmP.
//   S: warps 0..9: squash + tq update + next norms.
// ---------------------------------------------------------------------------
#define SMF_TV 0
#define SMF_HV (SMF_TV + NC * DP * 4)
#define SMF_PART (SMF_HV + GQ * NC * DP)
#define SMF_A (SMF_PART + GQ * NCHUNK * NC * IC)
#define SMF_P (SMF_A + GQ * NC * IC)
#define SMF_DSP (SMF_P + GQ * NC * IC)
#define SMF_NUMS (SMF_DSP + GQ * NC * IC)
#define SMF_MEAN (SMF_NUMS + GQ * NC * IC)
#define SMF_NORM (SMF_MEAN + NC * IC)
#define SMF_RNQ (SMF_NORM + NC * IC)
#define SMF_STQ (SMF_RNQ + GQ * NC)
#define SMF_TOTAL (SMF_STQ + GQ * NC)

__global__ __launch_bounds__(1024) void routing_kernel(
    const float* __restrict__ hmT, const float* __restrict__ hmP,
    const float* __restrict__ meanA, const float* __restrict__ normA,
    const float* __restrict__ hq, float* __restrict__ out) {
  extern __shared__ float smem[];
  float4* tv4 = (float4*)(smem + SMF_TV);  // [c*DP+d] = {tq0,v0,tq1,v1}
  float* hv = smem + SMF_HV;
  float* part6 = smem + SMF_PART;
  float* a_s = smem + SMF_A;
  float* p_s = smem + SMF_P;
  float* dsp_s = smem + SMF_DSP;
  float* num_s = smem + SMF_NUMS;
  float* mean_s = smem + SMF_MEAN;
  float* norm_s = smem + SMF_NORM;
  float* rnq = smem + SMF_RNQ;
  float* stq = smem + SMF_STQ;

  const int q0 = blockIdx.x * GQ;
  const int t = threadIdx.x;
  const int w = t >> 5, lane = t & 31;

  for (int j = t; j < NC * DP; j += 1024) {
    int c = j / DP, d = j - c * DP;
    float x0 = 0.f, x1 = 0.f;
    if (d < DD) {
      x0 = hq[q0 * CDP + c * DD + d];
      x1 = hq[(q0 + 1) * CDP + c * DD + d];
    }
    tv4[j] = make_float4(x0, 0.f, x1, 0.f);
  }
  for (int j = t; j < GQ * NC * IC; j += 1024) a_s[j] = 0.f;
  for (int j = t; j < NC * IC; j += 1024) {
    mean_s[j] = meanA[j];
    norm_s[j] = normA[j];
  }
  __syncthreads();

  // prologue: initial norms (warps 0..9: qq=w/5, c=w%5)
  if (w < GQ * NC) {
    const int qq = w / NC, c = w - qq * NC;
    const float4* tvc = tv4 + c * DP;
    float s = 0.f, s2 = 0.f;
    for (int d = lane; d < DD; d += 32) {
      float4 v = tvc[d];
      float x = qq ? v.z : v.x;
      s += x;
      s2 += x * x;
    }
    s = warp_sum(s);
    s2 = warp_sum(s2);
    if (lane == 0) {
      float mean = s * (1.f / DD);
      rnq[qq * NC + c] = sqrtf(fmaxf(s2 - DD * mean * mean, 0.f));
      stq[qq * NC + c] = s;
    }
  }
  __syncthreads();

  for (int r = 0; r < 3; ++r) {
    // ---- phase A: 25 warps (ch, c), BOTH queries, one sweep ----
    if (w < NCHUNK * NC) {
      const int c = w % NC;
      const int ch = w / NC;
      const int d0 = ch * DCH;
      const float4* base = (const float4*)hmT + (c * DDP + d0) * (IC / 4) + lane;
      const float4* tvc = tv4 + c * DP + d0;
      const int o0 = ch * (NC * IC) + c * IC + 4 * lane;
      const int o1 = NCHUNK * NC * IC + o0;
      float4 a0 = {0, 0, 0, 0}, a1 = {0, 0, 0, 0};
      if (r == 0) {
        // dot hm . tq (fields .x / .z)
#pragma unroll
        for (int b = 0; b < DCH / 4; ++b) {
          float4 h0 = base[(4 * b + 0) * (IC / 4)];
          float4 h1 = base[(4 * b + 1) * (IC / 4)];
          float4 h2 = base[(4 * b + 2) * (IC / 4)];
          float4 h3 = base[(4 * b + 3) * (IC / 4)];
          float4 t0 = tvc[4 * b + 0];
          float4 t1 = tvc[4 * b + 1];
          float4 t2 = tvc[4 * b + 2];
          float4 t3 = tvc[4 * b + 3];
          a0.x += h0.x * t0.x; a0.y += h0.y * t0.x; a0.z += h0.z * t0.x; a0.w += h0.w * t0.x;
          a1.x += h0.x * t0.z; a1.y += h0.y * t0.z; a1.z += h0.z * t0.z; a1.w += h0.w * t0.z;
          a0.x += h1.x * t1.x; a0.y += h1.y * t1.x; a0.z += h1.z * t1.x; a0.w += h1.w * t1.x;
          a1.x += h1.x * t1.z; a1.y += h1.y * t1.z; a1.z += h1.z * t1.z; a1.w += h1.w * t1.z;
          a0.x += h2.x * t2.x; a0.y += h2.y * t2.x; a0.z += h2.z * t2.x; a0.w += h2.w * t2.x;
          a1.x += h2.x * t2.z; a1.y += h2.y * t2.z; a1.z += h2.z * t2.z; a1.w += h2.w * t2.z;
          a0.x += h3.x * t3.x; a0.y += h3.y * t3.x; a0.z += h3.z * t3.x; a0.w += h3.w * t3.x;
          a1.x += h3.x * t3.z; a1.y += h3.y * t3.z; a1.z += h3.z * t3.z; a1.w += h3.w * t3.z;
        }
      } else {
        // dot hm . v (fields .y / .w)
#pragma unroll
        for (int b = 0; b < DCH / 4; ++b) {
          float4 h0 = base[(4 * b + 0) * (IC / 4)];
          float4 h1 = base[(4 * b + 1) * (IC / 4)];
          float4 h2 = base[(4 * b + 2) * (IC / 4)];
          float4 h3 = base[(4 * b + 3) * (IC / 4)];
          float4 t0 = tvc[4 * b + 0];
          float4 t1 = tvc[4 * b + 1];
          float4 t2 = tvc[4 * b + 2];
          float4 t3 = tvc[4 * b + 3];
          a0.x += h0.x * t0.y; a0.y += h0.y * t0.y; a0.z += h0.z * t0.y; a0.w += h0.w * t0.y;
          a1.x += h0.x * t0.w; a1.y += h0.y * t0.w; a1.z += h0.z * t0.w; a1.w += h0.w * t0.w;
          a0.x += h1.x * t1.y; a0.y += h1.y * t1.y; a0.z += h1.z * t1.y; a0.w += h1.w * t1.y;
          a1.x += h1.x * t1.w; a1.y += h1.y * t1.w; a1.z += h1.z * t1.w; a1.w += h1.w * t1.w;
          a0.x += h2.x * t2.y; a0.y += h2.y * t2.y; a0.z += h2.z * t2.y; a0.w += h2.w * t2.y;
          a1.x += h2.x * t2.w; a1.y += h2.y * t2.w; a1.z += h2.z * t2.w; a1.w += h2.w * t2.w;
          a0.x += h3.x * t3.y; a0.y += h3.y * t3.y; a0.z += h3.z * t3.y; a0.w += h3.w * t3.y;
          a1.x += h3.x * t3.w; a1.y += h3.y * t3.w; a1.z += h3.z * t3.w; a1.w += h3.w * t3.w;
        }
      }
      *(float4*)(part6 + o0) = a0;
      *(float4*)(part6 + o1) = a1;
    }
    __syncthreads();

    // ---- phase I: t < 256 ----
    if (t < GQ * IC) {
      const int qq = t >> 7, i = t & 127;
      const int qb = qq * NC * IC;
      const int q6 = qq * NCHUNK * NC * IC;
      float p[NC];
      if (r == 0) {
#pragma unroll
        for (int c = 0; c < NC; ++c) {
          int o = c * IC + i;
          float num = 0.f;
#pragma unroll
          for (int ch = 0; ch < NCHUNK; ++ch) num += part6[q6 + ch * NC * IC + o];
          num_s[qb + o] = num;  // raw (uncentered)
          num -= mean_s[o] * stq[qq * NC + c];
          float den = norm_s[o] * rnq[qq * NC + c] + EPSF;
          float x = __fdividef(num, den);
          float e2 = __expf(2.f * x);
          p[c] = __fdividef(e2 - 1.f, e2 + 1.f);
          p_s[qb + o] = p[c];
          dsp_s[qb + o] = 0.2f + p[c];
        }
      } else {
        float a[NC];
        float amax = -1e30f;
#pragma unroll
        for (int c = 0; c < NC; ++c) {
          int o = c * IC + i;
          float mdv = 0.f;
#pragma unroll
          for (int ch = 0; ch < NCHUNK; ++ch) mdv += part6[q6 + ch * NC * IC + o];
          float num = 0.5f * (num_s[qb + o] + mdv);  // recurrence
          num_s[qb + o] = num;
          float po = p_s[qb + o];
          float av = a_s[qb + o] + po * mdv;
          a_s[qb + o] = av;
          a[c] = av;
          float numc = num - mean_s[o] * stq[qq * NC + c];
          float den = norm_s[o] * rnq[qq * NC + c] + EPSF;
          float x = __fdividef(numc, den);
          float e2 = __expf(2.f * x);
          p[c] = __fdividef(e2 - 1.f, e2 + 1.f);
          p_s[qb + o] = p[c];
          amax = fmaxf(amax, av);
        }
        float es = 0.f, e[NC];
#pragma unroll
        for (int c = 0; c < NC; ++c) {
          e[c] = __expf(a[c] - amax);
          es += e[c];
        }
        float inv = __fdividef(1.f, es);
#pragma unroll
        for (int c = 0; c < NC; ++c) dsp_s[qb + c * IC + i] = e[c] * inv + p[c];
      }
    }
    __syncthreads();

    // ---- phase B: t < 800, thread per (qq,c,d2), 8-i batches ----
    if (t < GQ * NC * (DP / 2)) {
      const int qq = t / (NC * (DP / 2));
      const int rem = t - qq * (NC * (DP / 2));
      const int c = rem / (DP / 2);
      const int d2 = rem - c * (DP / 2);
      const float2* hp = (const float2*)hmP + c * (DP / 2) + d2;
      const float4* wq4 = (const float4*)(dsp_s + qq * NC * IC + c * IC);
      float ax = 0.f, ay = 0.f;
#pragma unroll 2
      for (int ib = 0; ib < IC / 8; ++ib) {
        float4 g0 = wq4[2 * ib];
        float4 g1 = wq4[2 * ib + 1];
        float2 f0 = hp[(8 * ib + 0) * (ROWP / 2)];
        float2 f1 = hp[(8 * ib + 1) * (ROWP / 2)];
        float2 f2 = hp[(8 * ib + 2) * (ROWP / 2)];
        float2 f3 = hp[(8 * ib + 3) * (ROWP / 2)];
        float2 f4 = hp[(8 * ib + 4) * (ROWP / 2)];
        float2 f5 = hp[(8 * ib + 5) * (ROWP / 2)];
        float2 f6 = hp[(8 * ib + 6) * (ROWP / 2)];
        float2 f7 = hp[(8 * ib + 7) * (ROWP / 2)];
        ax += f0.x * g0.x + f1.x * g0.y + f2.x * g0.z + f3.x * g0.w;
        ay += f0.y * g0.x + f1.y * g0.y + f2.y * g0.z + f3.y * g0.w;
        ax += f4.x * g1.x + f5.x * g1.y + f6.x * g1.z + f7.x * g1.w;
        ay += f4.y * g1.x + f5.y * g1.y + f6.y * g1.z + f7.y * g1.w;
      }
      hv[qq * NC * DP + c * DP + 2 * d2] = ax;
      hv[qq * NC * DP + c * DP + 2 * d2 + 1] = ay;
    }
    __syncthreads();

    // ---- phase S: squash + next tq + next norms (warps 0..9) ----
    if (w < GQ * NC) {
      const int qq = w / NC, c = w - qq * NC;
      const float* hvc = hv + qq * NC * DP + c * DP;
      float s2 = 0.f;
      for (int d = lane; d < DD; d += 32) {
        float x = hvc[d];
        s2 += x * x;
      }
      s2 = warp_sum(s2);
      float sc = s2 / ((1.f + s2) * sqrtf(s2 + EPSF));
      if (r < 2) {
        float2* tvh = (float2*)(tv4 + c * DP) + qq;  // (tq,v) half of float4
        float s = 0.f, sq = 0.f;
        for (int d = lane; d < DD; d += 32) {
          float vd = hvc[d] * sc;
          float x = (tvh[2 * d].x + vd) * 0.5f;
          tvh[2 * d] = make_float2(x, vd);
          s += x;
          sq += x * x;
        }
        s = warp_sum(s);
        sq = warp_sum(sq);
        if (lane == 0) {
          float mean = s * (1.f / DD);
          rnq[qq * NC + c] = sqrtf(fmaxf(sq - DD * mean * mean, 0.f));
          stq[qq * NC + c] = s;
        }
      } else {
        for (int d = lane; d < DD; d += 32)
          out[(q0 + qq) * CD + c * DD + d] = hvc[d] * sc;
      }
    }
    __syncthreads();
  }
}

// ---------------------------------------------------------------------------
extern "C" void kernel_launch(void* const* d_in, const int* in_sizes, int n_in,
                              void* d_out, int out_size) {
  const float *m = nullptr, *q = nullptr, *W = nullptr, *b = nullptr;
  for (int i = 0; i < n_in; ++i) {
    switch (in_sizes[i]) {
      case IC * KD: m = (const float*)d_in[i]; break;
      case NQV * KD: q = (const float*)d_in[i]; break;
      case KD * CD: W = (const float*)d_in[i]; break;
      case CD: b = (const float*)d_in[i]; break;
      default: break;
    }
  }
  float* out = (float*)d_out;

  void *p_hm, *p_hq, *p_hmT, *p_hmP, *p_mean, *p_norm, *p_wp;
  cudaGetSymbolAddress(&p_hm, g_hm);
  cudaGetSymbolAddress(&p_hq, g_hq);
  cudaGetSymbolAddress(&p_hmT, g_hmT);
  cudaGetSymbolAddress(&p_hmP, g_hmP);
  cudaGetSymbolAddress(&p_mean, g_mean);
  cudaGetSymbolAddress(&p_norm, g_norm);
  cudaGetSymbolAddress(&p_wp, g_Wp);

  static bool attr_set = false;
  if (!attr_set) {
    cudaFuncSetAttribute(routing_kernel,
                         cudaFuncAttributeMaxDynamicSharedMemorySize,
                         SMF_TOTAL * 4);
    attr_set = true;
  }

  wpad_kernel<<<(KD * CDP + 255) / 256, 256>>>(W, (float*)p_wp);

  dim3 gg(CDP / BN, (IC + NQV) / BM);  // (24, 12) = 288 blocks
  gemm_kernel<<<gg, 128>>>(m, q, (const float*)p_wp, b, (float*)p_hm,
                           (float*)p_hq);

  prep_kernel<<<180, 256>>>((const float*)p_hm, (float*)p_hmP, (float*)p_hmT,
                            (float*)p_mean, (float*)p_norm);

  routing_kernel<<<NQV / GQ, 1024, SMF_TOTAL * 4>>>(
      (const float*)p_hmT, (const float*)p_hmP, (const float*)p_mean,
      (const float*)p_norm, (const float*)p_hq, out);
}

// round 13
// speedup vs baseline: 1.1098x; 1.1098x over previous
#include <cuda_runtime.h>
#include <math.h>

#define IC 128
#define NC 5
#define DD 153
#define DP 160      // padded capsule dim
#define DDP 160     // padded d-dim for hmT
#define CD 765
#define CDP 768     // padded row stride for GEMM outputs / Wp
#define ROWP 800    // NC*DP
#define KD 768
#define NQV 256
#define EPSF 1e-8f
#define NCHUNK 3
#define DCH 51      // 3*51 = 153 = DD

__device__ __align__(16) float g_hm[IC * CDP];        // hat_m fp32 (GEMM out)
__device__ __align__(16) float g_hq[NQV * CDP];       // hat_q fp32
__device__ __align__(16) float g_hmT[NC * DDP * IC];  // [c][dpad][i] fp32
__device__ __align__(16) float g_hmP[IC * ROWP];      // [i][c][dp] fp32, pads 0
__device__ __align__(16) float g_mean[NC * IC];       // [c][i]
__device__ __align__(16) float g_norm[NC * IC];       // [c][i]
__device__ __align__(16) float g_Wp[KD * CDP];        // zero-padded W

__device__ __forceinline__ float warp_sum(float v) {
#pragma unroll
  for (int o = 16; o; o >>= 1) v += __shfl_xor_sync(0xffffffffu, v, o);
  return v;
}

// ---------------------------------------------------------------------------
// Pad W [768][765] -> Wp [768][768]
// ---------------------------------------------------------------------------
__global__ __launch_bounds__(256) void wpad_kernel(const float* __restrict__ W,
                                                   float* __restrict__ Wp) {
  int idx = blockIdx.x * 256 + threadIdx.x;
  if (idx < KD * CDP) {
    int k = idx / CDP, c = idx - k * CDP;
    Wp[idx] = (c < CD) ? W[k * CD + c] : 0.f;
  }
}

// ---------------------------------------------------------------------------
// GEMM: 32x32 tiles, grid (24,12)=288 blocks, 128 threads, 4x2 reg tile.
// ---------------------------------------------------------------------------
#define BM 32
#define BN 32
#define BK 32

__global__ __launch_bounds__(128) void gemm_kernel(
    const float* __restrict__ Am, const float* __restrict__ Aq,
    const float* __restrict__ Wp, const float* __restrict__ bias,
    float* __restrict__ Om, float* __restrict__ Oq) {
  __shared__ float As[BK][BM];
  __shared__ float Bs[BK][BN];
  const int t = threadIdx.x;
  const int row0 = blockIdx.y * BM;
  const int c0 = blockIdx.x * BN;

  const float* A;
  float* O;
  if (row0 < IC) { A = Am + row0 * KD; O = Om + row0 * CDP; }
  else           { A = Aq + (row0 - IC) * KD; O = Oq + (row0 - IC) * CDP; }

  const int ar = t >> 3, akc = (t & 7) << 2;
  const int br = t >> 3, bc = (t & 7) << 2;
  const int ty = t >> 4, tx = t & 15;

  float acc[4][2] = {};

  for (int k0 = 0; k0 < KD; k0 += BK) {
#pragma unroll
    for (int h = 0; h < 2; ++h) {
      float4 av = *(const float4*)(A + (ar + 16 * h) * KD + k0 + akc);
      As[akc + 0][ar + 16 * h] = av.x;
      As[akc + 1][ar + 16 * h] = av.y;
      As[akc + 2][ar + 16 * h] = av.z;
      As[akc + 3][ar + 16 * h] = av.w;
      *(float4*)&Bs[br + 16 * h][bc] =
          *(const float4*)(Wp + (k0 + br + 16 * h) * CDP + c0 + bc);
    }
    __syncthreads();
#pragma unroll
    for (int kk = 0; kk < BK; ++kk) {
      float4 a4 = *(const float4*)&As[kk][ty << 2];
      float b0 = Bs[kk][tx << 1];
      float b1 = Bs[kk][(tx << 1) + 1];
      acc[0][0] += a4.x * b0; acc[0][1] += a4.x * b1;
      acc[1][0] += a4.y * b0; acc[1][1] += a4.y * b1;
      acc[2][0] += a4.z * b0; acc[2][1] += a4.z * b1;
      acc[3][0] += a4.w * b0; acc[3][1] += a4.w * b1;
    }
    __syncthreads();
  }

#pragma unroll
  for (int rr = 0; rr < 4; ++rr) {
    int lr = (ty << 2) + rr;
#pragma unroll
    for (int j = 0; j < 2; ++j) {
      int c = c0 + (tx << 1) + j;
      if (c < CD) O[lr * CDP + c] = acc[rr][j] + bias[c];
    }
  }
}

// ---------------------------------------------------------------------------
// Prep: blocks 0..79 = stats + hmP fp32; blocks 80..179 = transpose fp32
// into d-padded hmT (zero rows for d in [153,160)).
// ---------------------------------------------------------------------------
__global__ __launch_bounds__(256) void prep_kernel(
    const float* __restrict__ hm, float* __restrict__ hmP,
    float* __restrict__ hmT, float* __restrict__ meanA,
    float* __restrict__ normA) {
  const int t = threadIdx.x;
  if (blockIdx.x < 80) {
    int g = blockIdx.x * 8 + (t >> 5);
    int lane = t & 31;
    int i = g / NC, c = g - i * NC;
    const float* row = hm + i * CDP + c * DD;
    float vals[5];
    float s = 0.f, s2 = 0.f;
#pragma unroll
    for (int k = 0; k < 5; ++k) {
      int d = lane + 32 * k;
      float x = (d < DD) ? row[d] : 0.f;
      vals[k] = x;
      s += x;
      s2 += x * x;
    }
    s = warp_sum(s);
    s2 = warp_sum(s2);
    float mean = s * (1.f / DD);
    if (lane == 0) {
      meanA[c * IC + i] = mean;
      normA[c * IC + i] = sqrtf(fmaxf(s2 - DD * mean * mean, 0.f));
    }
#pragma unroll
    for (int k = 0; k < 5; ++k) {
      int d = lane + 32 * k;
      hmP[i * ROWP + c * DP + d] = vals[k];
    }
  } else {
    __shared__ float sm[32][33];
    int bx = blockIdx.x - 80;
    int c = bx / 20;
    int rem = bx - c * 20;
    int i0 = (rem / 5) * 32;
    int d0 = (rem % 5) * 32;
    int tx = t & 31, ty = t >> 5;
#pragma unroll
    for (int k = 0; k < 4; ++k) {
      int i = i0 + ty + 8 * k;
      int d = d0 + tx;
      sm[tx][ty + 8 * k] = (d < DD) ? hm[i * CDP + c * DD + d] : 0.f;
    }
    __syncthreads();
#pragma unroll
    for (int k = 0; k < 4; ++k) {
      int d = d0 + ty + 8 * k;
      hmT[(c * DDP + d) * IC + i0 + tx] = sm[ty + 8 * k][tx];  // zeros d>=153
    }
  }
}

// ---------------------------------------------------------------------------
// Routing v13: ONE query per block, 512 threads, grid 256 (>= 148 SMs, most
// SMs host 2 blocks whose phases interleave — cross-block latency hiding).
//   A: 15 warps (ch 0..2, c 0..4), 51 d's each, 4-d load batches; one hmT
//      load feeds num+mdv (8 FMA) when r>0.
//   I: t<128: per-i a-update/p/softmax/dsp.
//   B: t<400: thread per (c,d2), 8-i batches over hmP.
//   S: warps 0..4: squash + tq update + next norms.
// ---------------------------------------------------------------------------
#define SMF_TV 0
#define SMF_HV (SMF_TV + NC * DP * 2)
#define SMF_NUM (SMF_HV + NC * DP)
#define SMF_MDV (SMF_NUM + NCHUNK * NC * IC)
#define SMF_A (SMF_MDV + NCHUNK * NC * IC)
#define SMF_P (SMF_A + NC * IC)
#define SMF_DSP (SMF_P + NC * IC)
#define SMF_MEAN (SMF_DSP + NC * IC)
#define SMF_NORM (SMF_MEAN + NC * IC)
#define SMF_RNQ (SMF_NORM + NC * IC)
#define SMF_STQ (SMF_RNQ + NC)
#define SMF_TOTAL (SMF_STQ + NC)

__global__ __launch_bounds__(512) void routing_kernel(
    const float* __restrict__ hmT, const float* __restrict__ hmP,
    const float* __restrict__ meanA, const float* __restrict__ normA,
    const float* __restrict__ hq, float* __restrict__ out) {
  extern __shared__ float smem[];
  float2* tv = (float2*)(smem + SMF_TV);  // [c*DP+d] = {tq, v}
  float* hv = smem + SMF_HV;
  float* num3 = smem + SMF_NUM;
  float* mdv3 = smem + SMF_MDV;
  float* a_s = smem + SMF_A;
  float* p_s = smem + SMF_P;
  float* dsp_s = smem + SMF_DSP;
  float* mean_s = smem + SMF_MEAN;
  float* norm_s = smem + SMF_NORM;
  float* rnq = smem + SMF_RNQ;
  float* stq = smem + SMF_STQ;

  const int q = blockIdx.x;
  const int t = threadIdx.x;
  const int w = t >> 5, lane = t & 31;

  for (int j = t; j < NC * DP; j += 512) {
    int c = j / DP, d = j - c * DP;
    float x = (d < DD) ? hq[q * CDP + c * DD + d] : 0.f;
    tv[j] = make_float2(x, 0.f);
  }
  for (int j = t; j < NC * IC; j += 512) {
    a_s[j] = 0.f;
    mean_s[j] = meanA[j];
    norm_s[j] = normA[j];
  }
  __syncthreads();

  // prologue: initial norms (warps 0..4: c=w)
  if (w < NC) {
    const int c = w;
    const float2* tvc = tv + c * DP;
    float s = 0.f, s2 = 0.f;
    for (int d = lane; d < DD; d += 32) {
      float x = tvc[d].x;
      s += x;
      s2 += x * x;
    }
    s = warp_sum(s);
    s2 = warp_sum(s2);
    if (lane == 0) {
      float mean = s * (1.f / DD);
      rnq[c] = sqrtf(fmaxf(s2 - DD * mean * mean, 0.f));
      stq[c] = s;
    }
  }
  __syncthreads();

  for (int r = 0; r < 3; ++r) {
    // ---- phase A: 15 warps (ch, c), 4-d load batches ----
    if (w < NCHUNK * NC) {
      const int c = w % NC;
      const int ch = w / NC;
      const int d0 = ch * DCH;
      const float4* base = (const float4*)hmT + (c * DDP + d0) * (IC / 4) + lane;
      const float2* tvc = tv + c * DP + d0;
      const int o = ch * (NC * IC) + c * IC + 4 * lane;
      float4 an = {0, 0, 0, 0}, av = {0, 0, 0, 0};
      if (r == 0) {
#pragma unroll
        for (int b = 0; b < DCH / 4; ++b) {
          float4 h0 = base[(4 * b + 0) * (IC / 4)];
          float4 h1 = base[(4 * b + 1) * (IC / 4)];
          float4 h2 = base[(4 * b + 2) * (IC / 4)];
          float4 h3 = base[(4 * b + 3) * (IC / 4)];
          float t0 = tvc[4 * b + 0].x;
          float t1 = tvc[4 * b + 1].x;
          float t2 = tvc[4 * b + 2].x;
          float t3 = tvc[4 * b + 3].x;
          an.x += h0.x * t0; an.y += h0.y * t0; an.z += h0.z * t0; an.w += h0.w * t0;
          an.x += h1.x * t1; an.y += h1.y * t1; an.z += h1.z * t1; an.w += h1.w * t1;
          an.x += h2.x * t2; an.y += h2.y * t2; an.z += h2.z * t2; an.w += h2.w * t2;
          an.x += h3.x * t3; an.y += h3.y * t3; an.z += h3.z * t3; an.w += h3.w * t3;
        }
#pragma unroll
        for (int d = (DCH / 4) * 4; d < DCH; ++d) {
          float4 h = base[d * (IC / 4)];
          float tq = tvc[d].x;
          an.x += h.x * tq; an.y += h.y * tq; an.z += h.z * tq; an.w += h.w * tq;
        }
        *(float4*)(num3 + o) = an;
      } else {
#pragma unroll
        for (int b = 0; b < DCH / 4; ++b) {
          float4 h0 = base[(4 * b + 0) * (IC / 4)];
          float4 h1 = base[(4 * b + 1) * (IC / 4)];
          float4 h2 = base[(4 * b + 2) * (IC / 4)];
          float4 h3 = base[(4 * b + 3) * (IC / 4)];
          float2 t0 = tvc[4 * b + 0];
          float2 t1 = tvc[4 * b + 1];
          float2 t2 = tvc[4 * b + 2];
          float2 t3 = tvc[4 * b + 3];
          an.x += h0.x * t0.x; an.y += h0.y * t0.x; an.z += h0.z * t0.x; an.w += h0.w * t0.x;
          av.x += h0.x * t0.y; av.y += h0.y * t0.y; av.z += h0.z * t0.y; av.w += h0.w * t0.y;
          an.x += h1.x * t1.x; an.y += h1.y * t1.x; an.z += h1.z * t1.x; an.w += h1.w * t1.x;
          av.x += h1.x * t1.y; av.y += h1.y * t1.y; av.z += h1.z * t1.y; av.w += h1.w * t1.y;
          an.x += h2.x * t2.x; an.y += h2.y * t2.x; an.z += h2.z * t2.x; an.w += h2.w * t2.x;
          av.x += h2.x * t2.y; av.y += h2.y * t2.y; av.z += h2.z * t2.y; av.w += h2.w * t2.y;
          an.x += h3.x * t3.x; an.y += h3.y * t3.x; an.z += h3.z * t3.x; an.w += h3.w * t3.x;
          av.x += h3.x * t3.y; av.y += h3.y * t3.y; av.z += h3.z * t3.y; av.w += h3.w * t3.y;
        }
#pragma unroll
        for (int d = (DCH / 4) * 4; d < DCH; ++d) {
          float4 h = base[d * (IC / 4)];
          float2 tq = tvc[d];
          an.x += h.x * tq.x; an.y += h.y * tq.x; an.z += h.z * tq.x; an.w += h.w * tq.x;
          av.x += h.x * tq.y; av.y += h.y * tq.y; av.z += h.z * tq.y; av.w += h.w * tq.y;
        }
        *(float4*)(num3 + o) = an;
        *(float4*)(mdv3 + o) = av;
      }
    }
    __syncthreads();

    // ---- phase I: t < 128 ----
    if (t < IC) {
      const int i = t;
      float p[NC];
      if (r == 0) {
#pragma unroll
        for (int c = 0; c < NC; ++c) {
          int o = c * IC + i;
          float num = num3[o] + num3[NC * IC + o] + num3[2 * NC * IC + o];
          num -= mean_s[o] * stq[c];
          float den = norm_s[o] * rnq[c] + EPSF;
          float x = __fdividef(num, den);
          float e2 = __expf(2.f * x);
          p[c] = __fdividef(e2 - 1.f, e2 + 1.f);
          p_s[o] = p[c];
          dsp_s[o] = 0.2f + p[c];
        }
      } else {
        float a[NC];
        float amax = -1e30f;
#pragma unroll
        for (int c = 0; c < NC; ++c) {
          int o = c * IC + i;
          float num = num3[o] + num3[NC * IC + o] + num3[2 * NC * IC + o];
          float mdv = mdv3[o] + mdv3[NC * IC + o] + mdv3[2 * NC * IC + o];
          num -= mean_s[o] * stq[c];
          float po = p_s[o];
          float av = a_s[o] + po * mdv;
          a_s[o] = av;
          a[c] = av;
          float den = norm_s[o] * rnq[c] + EPSF;
          float x = __fdividef(num, den);
          float e2 = __expf(2.f * x);
          p[c] = __fdividef(e2 - 1.f, e2 + 1.f);
          p_s[o] = p[c];
          amax = fmaxf(amax, av);
        }
        float es = 0.f, e[NC];
#pragma unroll
        for (int c = 0; c < NC; ++c) {
          e[c] = __expf(a[c] - amax);
          es += e[c];
        }
        float inv = __fdividef(1.f, es);
#pragma unroll
        for (int c = 0; c < NC; ++c) dsp_s[c * IC + i] = e[c] * inv + p[c];
      }
    }
    __syncthreads();

    // ---- phase B: t < 400, thread per (c,d2), 8-i batches ----
    if (t < NC * (DP / 2)) {
      const int c = t / (DP / 2);
      const int d2 = t - c * (DP / 2);
      const float2* hp = (const float2*)hmP + c * (DP / 2) + d2;
      const float4* wq4 = (const float4*)(dsp_s + c * IC);
      float ax = 0.f, ay = 0.f;
#pragma unroll 2
      for (int ib = 0; ib < IC / 8; ++ib) {
        float4 g0 = wq4[2 * ib];
        float4 g1 = wq4[2 * ib + 1];
        float2 f0 = hp[(8 * ib + 0) * (ROWP / 2)];
        float2 f1 = hp[(8 * ib + 1) * (ROWP / 2)];
        float2 f2 = hp[(8 * ib + 2) * (ROWP / 2)];
        float2 f3 = hp[(8 * ib + 3) * (ROWP / 2)];
        float2 f4 = hp[(8 * ib + 4) * (ROWP / 2)];
        float2 f5 = hp[(8 * ib + 5) * (ROWP / 2)];
        float2 f6 = hp[(8 * ib + 6) * (ROWP / 2)];
        float2 f7 = hp[(8 * ib + 7) * (ROWP / 2)];
        ax += f0.x * g0.x + f1.x * g0.y + f2.x * g0.z + f3.x * g0.w;
        ay += f0.y * g0.x + f1.y * g0.y + f2.y * g0.z + f3.y * g0.w;
        ax += f4.x * g1.x + f5.x * g1.y + f6.x * g1.z + f7.x * g1.w;
        ay += f4.y * g1.x + f5.y * g1.y + f6.y * g1.z + f7.y * g1.w;
      }
      hv[c * DP + 2 * d2] = ax;
      hv[c * DP + 2 * d2 + 1] = ay;
    }
    __syncthreads();

    // ---- phase S: squash + next tq + next norms (warps 0..4) ----
    if (w < NC) {
      const int c = w;
      const float* hvc = hv + c * DP;
      float s2 = 0.f;
      for (int d = lane; d < DD; d += 32) {
        float x = hvc[d];
        s2 += x * x;
      }
      s2 = warp_sum(s2);
      float sc = s2 / ((1.f + s2) * sqrtf(s2 + EPSF));
      if (r < 2) {
        float2* tvc = tv + c * DP;
        float s = 0.f, sq = 0.f;
        for (int d = lane; d < DD; d += 32) {
          float vd = hvc[d] * sc;
          float x = (tvc[d].x + vd) * 0.5f;
          tvc[d] = make_float2(x, vd);
          s += x;
          sq += x * x;
        }
        s = warp_sum(s);
        sq = warp_sum(sq);
        if (lane == 0) {
          float mean = s * (1.f / DD);
          rnq[c] = sqrtf(fmaxf(sq - DD * mean * mean, 0.f));
          stq[c] = s;
        }
      } else {
        for (int d = lane; d < DD; d += 32)
          out[q * CD + c * DD + d] = hvc[d] * sc;
      }
    }
    __syncthreads();
  }
}

// ---------------------------------------------------------------------------
extern "C" void kernel_launch(void* const* d_in, const int* in_sizes, int n_in,
                              void* d_out, int out_size) {
  const float *m = nullptr, *q = nullptr, *W = nullptr, *b = nullptr;
  for (int i = 0; i < n_in; ++i) {
    switch (in_sizes[i]) {
      case IC * KD: m = (const float*)d_in[i]; break;
      case NQV * KD: q = (const float*)d_in[i]; break;
      case KD * CD: W = (const float*)d_in[i]; break;
      case CD: b = (const float*)d_in[i]; break;
      default: break;
    }
  }
  float* out = (float*)d_out;

  void *p_hm, *p_hq, *p_hmT, *p_hmP, *p_mean, *p_norm, *p_wp;
  cudaGetSymbolAddress(&p_hm, g_hm);
  cudaGetSymbolAddress(&p_hq, g_hq);
  cudaGetSymbolAddress(&p_hmT, g_hmT);
  cudaGetSymbolAddress(&p_hmP, g_hmP);
  cudaGetSymbolAddress(&p_mean, g_mean);
  cudaGetSymbolAddress(&p_norm, g_norm);
  cudaGetSymbolAddress(&p_wp, g_Wp);

  static bool attr_set = false;
  if (!attr_set) {
    cudaFuncSetAttribute(routing_kernel,
                         cudaFuncAttributeMaxDynamicSharedMemorySize,
                         SMF_TOTAL * 4);
    attr_set = true;
  }

  wpad_kernel<<<(KD * CDP + 255) / 256, 256>>>(W, (float*)p_wp);

  dim3 gg(CDP / BN, (IC + NQV) / BM);  // (24, 12) = 288 blocks
  gemm_kernel<<<gg, 128>>>(m, q, (const float*)p_wp, b, (float*)p_hm,
                           (float*)p_hq);

  prep_kernel<<<180, 256>>>((const float*)p_hm, (float*)p_hmP, (float*)p_hmT,
                            (float*)p_mean, (float*)p_norm);

  routing_kernel<<<NQV, 512, SMF_TOTAL * 4>>>(
      (const float*)p_hmT, (const float*)p_hmP, (const float*)p_mean,
      (const float*)p_norm, (const float*)p_hq, out);
}